// round 1
// baseline (speedup 1.0000x reference)
#include <cuda_runtime.h>
#include <cuda_fp16.h>
#include <math.h>

#define N_NODES 32768
#define N_EDGES 8192
#define ND 128
#define ED 128
#define HD 64
#define OD 128
#define NH 4
#define EPSV 1e-8f

// ---------------- scratch (device globals; no allocation allowed) ----------------
__device__ __half g_te[(size_t)N_EDGES * 256];          // te for all 4 heads, [E][h*64+c], fp16 (4MB, L2-resident)
__device__ float  g_agg[(size_t)N_NODES * 256];         // deg-normalized agg for all heads  (32MB)
__device__ float  g_bufA[(size_t)N_NODES * OD];         // upd scratch
__device__ float  g_bufB[(size_t)N_NODES * OD];         // chained x scratch
__device__ float  g_cmin[NH * OD];
__device__ float  g_cmax[NH * OD];

// ---------------- helpers ----------------
__device__ __forceinline__ void atomicMinF(float* addr, float value) {
    if (value >= 0.f) atomicMin((int*)addr, __float_as_int(value));
    else              atomicMax((unsigned int*)addr, __float_as_uint(value));
}
__device__ __forceinline__ void atomicMaxF(float* addr, float value) {
    if (value >= 0.f) atomicMax((int*)addr, __float_as_int(value));
    else              atomicMin((unsigned int*)addr, __float_as_uint(value));
}

// ---------------- kernel 0: init min/max slots ----------------
__global__ void init_minmax_kernel(float* cmin, float* cmax) {
    int t = threadIdx.x;  // 512 threads = NH*OD
    cmin[t] =  __int_as_float(0x7f800000);   // +inf
    cmax[t] = -__int_as_float(0x7f800000);   // -inf
}

// ---------------- kernel 1: te_all = edge_features @ edgeW[h] + edgeB[h], all heads, fp16 out ----------------
// grid: E/32 blocks, 256 threads. thread t -> head h=t/64, col c=t%64; 32 edges per block.
__global__ void te_kernel(const float* __restrict__ ef, const float* __restrict__ edgeW,
                          const float* __restrict__ edgeB, __half* __restrict__ te) {
    __shared__ float sef[32][ED + 1];
    int t = threadIdx.x;
    int e0 = blockIdx.x * 32;

#pragma unroll
    for (int i = 0; i < 16; i++) {                // 32*128 = 4096 floats
        int L = i * 256 + t;
        int r = L >> 7, q = L & 127;
        sef[r][q] = ef[(size_t)(e0 + r) * ED + q];
    }
    __syncthreads();

    int h = t >> 6, c = t & 63;
    const float* W = edgeW + (size_t)h * ED * HD + c;   // stride HD over k
    float acc[32];
#pragma unroll
    for (int r = 0; r < 32; r++) acc[r] = 0.f;

    for (int k = 0; k < ED; k++) {
        float w = __ldg(W + k * HD);
#pragma unroll
        for (int r = 0; r < 32; r++) acc[r] += sef[r][k] * w;
    }
    float b = edgeB[h * HD + c];
#pragma unroll
    for (int r = 0; r < 32; r++)
        te[(size_t)(e0 + r) * 256 + t] = __float2half(acc[r] + b);
}

// ---------------- kernel 2: the big one. one block per node row. ----------------
// Phase 1: stream 32KB incidence row (streaming hint, keep te in L2), compact nonzero edge ids in smem.
// Phase 2: each of 256 threads owns one of the 256 output cols; gather-accumulate te rows (fp16, fp32 acc).
__global__ void scan_kernel(const float* __restrict__ inc, const __half* __restrict__ te,
                            float* __restrict__ agg) {
    __shared__ int s_idx[512];
    __shared__ int s_cnt;
    int t = threadIdx.x;
    int n = blockIdx.x;
    if (t == 0) s_cnt = 0;
    __syncthreads();

    const float4* row = (const float4*)(inc + (size_t)n * N_EDGES);
#pragma unroll
    for (int i = 0; i < 8; i++) {                 // 8192/4 = 2048 float4 / 256 threads
        int j = i * 256 + t;
        float4 v = __ldcs(row + j);
        int e0 = j * 4;
        if (v.x != 0.f) s_idx[atomicAdd(&s_cnt, 1)] = e0;
        if (v.y != 0.f) s_idx[atomicAdd(&s_cnt, 1)] = e0 + 1;
        if (v.z != 0.f) s_idx[atomicAdd(&s_cnt, 1)] = e0 + 2;
        if (v.w != 0.f) s_idx[atomicAdd(&s_cnt, 1)] = e0 + 3;
    }
    __syncthreads();

    int cnt = min(s_cnt, 512);
    float inv = 1.f / ((float)cnt + EPSV);        // incidence values are exactly 1.0 -> deg == count

    float a0 = 0.f, a1 = 0.f, a2 = 0.f, a3 = 0.f;
    int m = 0;
    for (; m + 4 <= cnt; m += 4) {
        a0 += __half2float(__ldg(&te[(size_t)s_idx[m + 0] * 256 + t]));
        a1 += __half2float(__ldg(&te[(size_t)s_idx[m + 1] * 256 + t]));
        a2 += __half2float(__ldg(&te[(size_t)s_idx[m + 2] * 256 + t]));
        a3 += __half2float(__ldg(&te[(size_t)s_idx[m + 3] * 256 + t]));
    }
    for (; m < cnt; m++)
        a0 += __half2float(__ldg(&te[(size_t)s_idx[m] * 256 + t]));

    agg[(size_t)n * 256 + t] = ((a0 + a1) + (a2 + a3)) * inv;
}

// ---------------- kernel 3: fused per-head transform ----------------
// block = 256 threads, 64 nodes per block.
//   tn = x @ nodeW[h] + nodeB[h]
//   s  = (tn+agg) @ attnW[h] + attnB[h];  g = sigmoid(leakyrelu(s,0.2))
//   u  = g*agg + tn
//   upd = u @ outW[h] + outB[h]           -> global + per-column min/max atomics
__global__ void head_kernel(const float* __restrict__ x, const float* __restrict__ agg,
                            const float* __restrict__ nodeW, const float* __restrict__ nodeB,
                            const float* __restrict__ attnW, const float* __restrict__ attnB,
                            const float* __restrict__ outW,  const float* __restrict__ outB,
                            int h, float* __restrict__ upd,
                            float* __restrict__ cmin, float* __restrict__ cmax) {
    extern __shared__ float sm[];
    float* sx    = sm;                    // [64][129] x tile
    float* sw    = sx + 64 * 129;         // 8192 floats: nodeW (stage2), then outW (stage3)
    float* stn   = sw + 8192;             // [64][65]: tn, then u (in place)
    float* sagg  = stn + 64 * 65;         // [64][65]
    float* sattn = sagg + 64 * 65;        // 64
    float* sg    = sattn + 64;            // 64
    float* sred  = sx;                    // reuse x region for min/max reduction (needs 2048)

    int t = threadIdx.x;
    int n0 = blockIdx.x * 64;

    // ---- stage 1: loads ----
#pragma unroll
    for (int i = 0; i < 32; i++) {        // x tile 64x128
        int L = i * 256 + t;
        int r = L >> 7, q = L & 127;
        sx[r * 129 + q] = x[(size_t)(n0 + r) * ND + q];
    }
    const float* nw = nodeW + (size_t)h * ND * HD;
#pragma unroll
    for (int i = 0; i < 32; i++) sw[i * 256 + t] = nw[i * 256 + t];
#pragma unroll
    for (int i = 0; i < 16; i++) {        // agg tile 64x64 (head slice)
        int L = i * 256 + t;
        int r = L >> 6, c = L & 63;
        sagg[r * 65 + c] = agg[(size_t)(n0 + r) * 256 + h * 64 + c];
    }
    if (t < 64) sattn[t] = attnW[h * 64 + t];
    __syncthreads();

    // ---- stage 2: tn = x @ nodeW + nodeB ----
    {
        int cg = t >> 4, ng = t & 15;
        int c0 = cg * 4, r0 = ng * 4;
        float acc[4][4];
#pragma unroll
        for (int i = 0; i < 4; i++)
#pragma unroll
            for (int j = 0; j < 4; j++) acc[i][j] = 0.f;

        for (int k = 0; k < ND; k++) {
            float4 wv = *(const float4*)&sw[k * 64 + c0];
#pragma unroll
            for (int i = 0; i < 4; i++) {
                float xv = sx[(r0 + i) * 129 + k];
                acc[i][0] += xv * wv.x;
                acc[i][1] += xv * wv.y;
                acc[i][2] += xv * wv.z;
                acc[i][3] += xv * wv.w;
            }
        }
        float nb0 = nodeB[h * HD + c0 + 0];
        float nb1 = nodeB[h * HD + c0 + 1];
        float nb2 = nodeB[h * HD + c0 + 2];
        float nb3 = nodeB[h * HD + c0 + 3];
#pragma unroll
        for (int i = 0; i < 4; i++) {
            stn[(r0 + i) * 65 + c0 + 0] = acc[i][0] + nb0;
            stn[(r0 + i) * 65 + c0 + 1] = acc[i][1] + nb1;
            stn[(r0 + i) * 65 + c0 + 2] = acc[i][2] + nb2;
            stn[(r0 + i) * 65 + c0 + 3] = acc[i][3] + nb3;
        }
    }
    __syncthreads();

    // ---- scores + gate (64 threads), overlapped with outW load (all threads) ----
    if (t < 64) {
        int r = t;
        float s = attnB[h];
        for (int c = 0; c < 64; c++)
            s += (stn[r * 65 + c] + sagg[r * 65 + c]) * sattn[c];
        s = (s >= 0.f) ? s : 0.2f * s;
        sg[r] = 1.f / (1.f + expf(-s));
    }
    const float* ow = outW + (size_t)h * HD * OD;
#pragma unroll
    for (int i = 0; i < 32; i++) sw[i * 256 + t] = ow[i * 256 + t];
    __syncthreads();

    // ---- u = g*agg + tn (in place over stn) ----
#pragma unroll
    for (int i = 0; i < 16; i++) {
        int L = i * 256 + t;
        int r = L >> 6, c = L & 63;
        stn[r * 65 + c] = sg[r] * sagg[r * 65 + c] + stn[r * 65 + c];
    }
    __syncthreads();

    // ---- stage 3: upd = u @ outW + outB, track per-column min/max ----
    {
        int jg = t & 31, rg = t >> 5;
        int j0 = jg * 4, rr0 = rg * 8;
        float4 acc3[8];
#pragma unroll
        for (int i = 0; i < 8; i++) acc3[i] = make_float4(0.f, 0.f, 0.f, 0.f);

        for (int c = 0; c < HD; c++) {
            float4 wv = *(const float4*)&sw[c * 128 + j0];
#pragma unroll
            for (int i = 0; i < 8; i++) {
                float uv = stn[(rr0 + i) * 65 + c];
                acc3[i].x += uv * wv.x;
                acc3[i].y += uv * wv.y;
                acc3[i].z += uv * wv.z;
                acc3[i].w += uv * wv.w;
            }
        }
        float4 ob = *(const float4*)&outB[h * OD + j0];
        float lmin0 =  3.4e38f, lmin1 =  3.4e38f, lmin2 =  3.4e38f, lmin3 =  3.4e38f;
        float lmax0 = -3.4e38f, lmax1 = -3.4e38f, lmax2 = -3.4e38f, lmax3 = -3.4e38f;
#pragma unroll
        for (int i = 0; i < 8; i++) {
            float4 o;
            o.x = acc3[i].x + ob.x; o.y = acc3[i].y + ob.y;
            o.z = acc3[i].z + ob.z; o.w = acc3[i].w + ob.w;
            *(float4*)&upd[(size_t)(n0 + rr0 + i) * OD + j0] = o;
            lmin0 = fminf(lmin0, o.x); lmax0 = fmaxf(lmax0, o.x);
            lmin1 = fminf(lmin1, o.y); lmax1 = fmaxf(lmax1, o.y);
            lmin2 = fminf(lmin2, o.z); lmax2 = fmaxf(lmax2, o.z);
            lmin3 = fminf(lmin3, o.w); lmax3 = fmaxf(lmax3, o.w);
        }
        __syncthreads();               // sx no longer needed; safe to reuse as sred
        float* smin = sred;            // [8][128]
        float* smax = sred + 1024;     // [8][128]
        smin[rg * 128 + j0 + 0] = lmin0; smax[rg * 128 + j0 + 0] = lmax0;
        smin[rg * 128 + j0 + 1] = lmin1; smax[rg * 128 + j0 + 1] = lmax1;
        smin[rg * 128 + j0 + 2] = lmin2; smax[rg * 128 + j0 + 2] = lmax2;
        smin[rg * 128 + j0 + 3] = lmin3; smax[rg * 128 + j0 + 3] = lmax3;
    }
    __syncthreads();
    if (t < 128) {
        float* smin = sred;
        float* smax = sred + 1024;
        float m = smin[t], M = smax[t];
#pragma unroll
        for (int rg = 1; rg < 8; rg++) {
            m = fminf(m, smin[rg * 128 + t]);
            M = fmaxf(M, smax[rg * 128 + t]);
        }
        atomicMinF(&cmin[t], m);
        atomicMaxF(&cmax[t], M);
    }
}

// ---------------- kernel 4: min-max normalize + relu ----------------
__global__ void norm_kernel(const float4* __restrict__ upd, const float* __restrict__ cmin,
                            const float* __restrict__ cmax, float4* __restrict__ dst) {
    __shared__ float sa[128], sb[128];
    int t = threadIdx.x;
    if (t < 128) {
        float mn = cmin[t], mx = cmax[t];
        sa[t] = 1.f / (mx - mn + EPSV);
        sb[t] = mn;
    }
    __syncthreads();
    int i = blockIdx.x * 256 + t;          // exactly N*OD/4 = 1,048,576 float4
    float4 v = upd[i];
    int c = (i & 31) * 4;
    float4 o;
    o.x = fmaxf(0.f, (v.x - sb[c + 0]) * sa[c + 0]);
    o.y = fmaxf(0.f, (v.y - sb[c + 1]) * sa[c + 1]);
    o.z = fmaxf(0.f, (v.z - sb[c + 2]) * sa[c + 2]);
    o.w = fmaxf(0.f, (v.w - sb[c + 3]) * sa[c + 3]);
    dst[i] = o;
}

// ---------------- launch ----------------
extern "C" void kernel_launch(void* const* d_in, const int* in_sizes, int n_in,
                              void* d_out, int out_size) {
    const float* nodeF = (const float*)d_in[0];
    const float* inc   = (const float*)d_in[1];
    const float* edgeF = (const float*)d_in[2];
    const float* nodeW = (const float*)d_in[3];
    const float* nodeB = (const float*)d_in[4];
    const float* edgeW = (const float*)d_in[5];
    const float* edgeB = (const float*)d_in[6];
    const float* attnW = (const float*)d_in[7];
    const float* attnB = (const float*)d_in[8];
    const float* outW  = (const float*)d_in[9];
    const float* outB  = (const float*)d_in[10];

    __half* te;  float *agg, *bufA, *bufB, *cmin, *cmax;
    cudaGetSymbolAddress((void**)&te,   g_te);
    cudaGetSymbolAddress((void**)&agg,  g_agg);
    cudaGetSymbolAddress((void**)&bufA, g_bufA);
    cudaGetSymbolAddress((void**)&bufB, g_bufB);
    cudaGetSymbolAddress((void**)&cmin, g_cmin);
    cudaGetSymbolAddress((void**)&cmax, g_cmax);

    size_t hk_smem = (size_t)(64 * 129 + 8192 + 64 * 65 + 64 * 65 + 64 + 64) * sizeof(float);
    cudaFuncSetAttribute(head_kernel, cudaFuncAttributeMaxDynamicSharedMemorySize, (int)hk_smem);

    init_minmax_kernel<<<1, NH * OD>>>(cmin, cmax);
    te_kernel<<<N_EDGES / 32, 256>>>(edgeF, edgeW, edgeB, te);
    scan_kernel<<<N_NODES, 256>>>(inc, te, agg);

    for (int h = 0; h < NH; h++) {
        const float* xin = (h == 0) ? nodeF : bufB;
        head_kernel<<<N_NODES / 64, 256, hk_smem>>>(xin, agg, nodeW, nodeB, attnW, attnB,
                                                    outW, outB, h, bufA,
                                                    cmin + h * 128, cmax + h * 128);
        float* dst = (h == NH - 1) ? (float*)d_out : bufB;
        norm_kernel<<<(N_NODES * OD / 4) / 256, 256>>>((const float4*)bufA,
                                                       cmin + h * 128, cmax + h * 128,
                                                       (float4*)dst);
    }
}